// round 6
// baseline (speedup 1.0000x reference)
#include <cuda_runtime.h>
#include <cstdint>

#define NTOK 16384
#define GRID 512
#define TPB  256

__device__ float g_pent[GRID];
__device__ float g_pstep[GRID];
__device__ unsigned int g_done;   // zero-initialized; reset by last block each launch

// ---- JAX threefry2x32 (20 rounds), exact key schedule ----
__device__ __forceinline__ uint2 tf2x32(uint32_t k0, uint32_t k1, uint32_t x0, uint32_t x1) {
    uint32_t k2 = k0 ^ k1 ^ 0x1BD11BDAu;
    x0 += k0; x1 += k1;
#define TFR(r) { x0 += x1; x1 = __funnelshift_l(x1, x1, (r)); x1 ^= x0; }
    TFR(13) TFR(15) TFR(26) TFR(6)
    x0 += k1; x1 += k2 + 1u;
    TFR(17) TFR(29) TFR(16) TFR(24)
    x0 += k2; x1 += k0 + 2u;
    TFR(13) TFR(15) TFR(26) TFR(6)
    x0 += k0; x1 += k1 + 3u;
    TFR(17) TFR(29) TFR(16) TFR(24)
    x0 += k1; x1 += k2 + 4u;
    TFR(13) TFR(15) TFR(26) TFR(6)
    x0 += k2; x1 += k0 + 5u;
#undef TFR
    return make_uint2(x0, x1);
}

// jax_threefry_partitionable=True, bit_width=32: bits1 ^ bits2
__device__ __forceinline__ uint32_t jax_bits(uint32_t k0, uint32_t k1, uint32_t i) {
    uint2 v = tf2x32(k0, k1, 0u, i);
    return v.x ^ v.y;
}

__device__ __forceinline__ float f12(uint32_t bits) {
    return __uint_as_float((bits >> 9) | 0x3f800000u);
}

// ---- packed f32x2 helpers (Blackwell) ----
__device__ __forceinline__ uint64_t pack2(float x) {
    uint64_t r; asm("mov.b64 %0, {%1, %1};" : "=l"(r) : "f"(x)); return r;
}
__device__ __forceinline__ void fma2(uint64_t& d, uint64_t a, uint64_t b) {
    asm("fma.rn.f32x2 %0, %1, %2, %0;" : "+l"(d) : "l"(a), "l"(b));
}
__device__ __forceinline__ uint64_t add2(uint64_t a, uint64_t b) {
    uint64_t r; asm("add.rn.f32x2 %0, %1, %2;" : "=l"(r) : "l"(a), "l"(b)); return r;
}
__device__ __forceinline__ uint64_t shfl_xor64(uint64_t v, int m) {
    uint32_t lo = (uint32_t)v, hi = (uint32_t)(v >> 32);
    lo = __shfl_xor_sync(0xFFFFFFFFu, lo, m);
    hi = __shfl_xor_sync(0xFFFFFFFFu, hi, m);
    return ((uint64_t)hi << 32) | lo;
}

__global__ __launch_bounds__(TPB)
void router_kernel(const float* __restrict__ x, const float* __restrict__ W,
                   const float* __restrict__ b, float* __restrict__ out) {
    extern __shared__ float smem[];
    float* sW  = smem;            // 16384 floats, swizzled [c][e] layout
    float* red = smem + 16384;    // [8][4][8][4] = 1024 floats: [warp][t][e][lane0-3]
    __shared__ float wred[16];
    __shared__ unsigned int s_last;

    int tid = threadIdx.x;

    // Stage W transposed into swizzled smem: logical float idx = c*8 + e
    for (int i = tid; i < 16384; i += TPB) {
        uint32_t A  = (uint32_t)i * 4u;
        uint32_t ph = A ^ ((A >> 3) & 0x70u);
        sW[ph >> 2] = W[(i & 7) * 2048 + (i >> 3)];
    }
    __syncthreads();

    int warp = tid >> 5, lane = tid & 31;
    int tok0 = blockIdx.x * 32 + warp * 4;
    const float4* xr = (const float4*)x + (size_t)tok0 * 512;

    uint32_t off[8];
#pragma unroll
    for (int k = 0; k < 4; k++) {
        off[2*k]   = (32u*(uint32_t)k)       ^ ((16u*(uint32_t)lane + 4u*(uint32_t)k)      & 0x70u);
        off[2*k+1] = (32u*(uint32_t)k + 16u) ^ ((16u*(uint32_t)lane + 4u*(uint32_t)k + 2u) & 0x70u);
    }

    // packed accumulators: accp[t][p] holds experts (2p, 2p+1) for token t
    uint64_t accp[4][4];
#pragma unroll
    for (int t = 0; t < 4; t++)
#pragma unroll
        for (int p = 0; p < 4; p++) accp[t][p] = 0ull;

    const char* sWb = (const char*)sW;

#pragma unroll 4
    for (int j = 0; j < 16; j++) {
        int cg = lane + 32 * j;
        float4 xv0 = xr[cg];
        float4 xv1 = xr[512  + cg];
        float4 xv2 = xr[1024 + cg];
        float4 xv3 = xr[1536 + cg];
        float xa0[4] = {xv0.x, xv0.y, xv0.z, xv0.w};
        float xa1[4] = {xv1.x, xv1.y, xv1.z, xv1.w};
        float xa2[4] = {xv2.x, xv2.y, xv2.z, xv2.w};
        float xa3[4] = {xv3.x, xv3.y, xv3.z, xv3.w};
        uint32_t base = (uint32_t)cg * 128u;
#pragma unroll
        for (int k = 0; k < 4; k++) {
            ulonglong2 wa = *(const ulonglong2*)(sWb + base + off[2*k]);     // experts (0,1),(2,3)
            ulonglong2 wb = *(const ulonglong2*)(sWb + base + off[2*k+1]);   // experts (4,5),(6,7)
            uint64_t xp;
            xp = pack2(xa0[k]); fma2(accp[0][0], xp, wa.x); fma2(accp[0][1], xp, wa.y);
                                fma2(accp[0][2], xp, wb.x); fma2(accp[0][3], xp, wb.y);
            xp = pack2(xa1[k]); fma2(accp[1][0], xp, wa.x); fma2(accp[1][1], xp, wa.y);
                                fma2(accp[1][2], xp, wb.x); fma2(accp[1][3], xp, wb.y);
            xp = pack2(xa2[k]); fma2(accp[2][0], xp, wa.x); fma2(accp[2][1], xp, wa.y);
                                fma2(accp[2][2], xp, wb.x); fma2(accp[2][3], xp, wb.y);
            xp = pack2(xa3[k]); fma2(accp[3][0], xp, wa.x); fma2(accp[3][1], xp, wa.y);
                                fma2(accp[3][2], xp, wb.x); fma2(accp[3][3], xp, wb.y);
        }
    }

    // 3-stage packed butterfly: each lane ends with sum over lanes {l mod 4}
#pragma unroll
    for (int t = 0; t < 4; t++)
#pragma unroll
        for (int p = 0; p < 4; p++) {
            uint64_t v = accp[t][p];
            v = add2(v, shfl_xor64(v, 16));
            v = add2(v, shfl_xor64(v, 8));
            v = add2(v, shfl_xor64(v, 4));
            accp[t][p] = v;
        }
    // lanes 0-3 stage their group sums: red[warp][t][e][lane]
    if (lane < 4) {
#pragma unroll
        for (int t = 0; t < 4; t++)
#pragma unroll
            for (int p = 0; p < 4; p++) {
                uint64_t v = accp[t][p];
                float lo = __uint_as_float((uint32_t)v);
                float hi = __uint_as_float((uint32_t)(v >> 32));
                red[((warp * 4 + t) * 8 + 2*p    ) * 4 + lane] = lo;
                red[((warp * 4 + t) * 8 + 2*p + 1) * 4 + lane] = hi;
            }
    }
    __syncthreads();

    // ---- Epilogue: one thread per (token, expert) ----
    {
        int e  = tid & 7;
        int tl = tid >> 3;
        int tok = blockIdx.x * 32 + tl;
        uint32_t idx = (uint32_t)tok * 8u + (uint32_t)e;

        float4 rv = *(const float4*)&red[(size_t)tid * 4];  // ((w*4+t)*8+e)*4 == tid*4
        float lg = (rv.x + rv.y) + (rv.z + rv.w) + b[e];

        float m = lg;
        m = fmaxf(m, __shfl_xor_sync(0xFFFFFFFFu, m, 1));
        m = fmaxf(m, __shfl_xor_sync(0xFFFFFFFFu, m, 2));
        m = fmaxf(m, __shfl_xor_sync(0xFFFFFFFFu, m, 4));

        uint32_t nb = jax_bits(0u, 1u, idx);
        float fl = f12(nb) - 1.0f;
        float u  = fmaxf(-0.99999994f, fmaf(fl, 2.0f, -0.99999994f));
        float nn = 1.41421356237f * erfinvf(u);
        float z  = (lg - m) + 0.05f * nn;
        z = fminf(50.0f, fmaxf(-50.0f, z));

        float m2 = z;
        m2 = fmaxf(m2, __shfl_xor_sync(0xFFFFFFFFu, m2, 1));
        m2 = fmaxf(m2, __shfl_xor_sync(0xFFFFFFFFu, m2, 2));
        m2 = fmaxf(m2, __shfl_xor_sync(0xFFFFFFFFu, m2, 4));
        float p = expf(z - m2);
        float s = p;
        s += __shfl_xor_sync(0xFFFFFFFFu, s, 1);
        s += __shfl_xor_sync(0xFFFFFFFFu, s, 2);
        s += __shfl_xor_sync(0xFFFFFFFFu, s, 4);
        float sp = p / s;

        float entt = -sp * logf(sp + 1e-8f);
        float stpt = sp * (float)e;

        uint32_t gb = jax_bits(0u, 2u, idx);
        float uu = f12(gb) - 1.0f;
        float g  = -logf(-logf(uu + 1e-8f) + 1e-8f) * 0.5f;
        float zg = z + g;
        float m3 = zg;
        m3 = fmaxf(m3, __shfl_xor_sync(0xFFFFFFFFu, m3, 1));
        m3 = fmaxf(m3, __shfl_xor_sync(0xFFFFFFFFu, m3, 2));
        m3 = fmaxf(m3, __shfl_xor_sync(0xFFFFFFFFu, m3, 4));
        float q = expf(zg - m3);
        float s3 = q;
        s3 += __shfl_xor_sync(0xFFFFFFFFu, s3, 1);
        s3 += __shfl_xor_sync(0xFFFFFFFFu, s3, 2);
        s3 += __shfl_xor_sync(0xFFFFFFFFu, s3, 4);

        out[idx] = q / s3;                 // routing_weights
        out[131074u + idx] = sp;           // soft_probs

        float es = entt, ts = stpt;
#pragma unroll
        for (int o = 16; o; o >>= 1) {
            es += __shfl_xor_sync(0xFFFFFFFFu, es, o);
            ts += __shfl_xor_sync(0xFFFFFFFFu, ts, o);
        }
        if (lane == 0) { wred[warp] = es; wred[8 + warp] = ts; }
    }
    __syncthreads();
    if (tid < 8) {
        float es = wred[tid], ts = wred[8 + tid];
#pragma unroll
        for (int o = 4; o; o >>= 1) {
            es += __shfl_xor_sync(0x000000FFu, es, o);
            ts += __shfl_xor_sync(0x000000FFu, ts, o);
        }
        if (tid == 0) { g_pent[blockIdx.x] = es; g_pstep[blockIdx.x] = ts; }
    }

    // ---- last-block finalization (deterministic: fixed reduction order) ----
    if (tid == 0) {
        __threadfence();
        unsigned int d = atomicAdd(&g_done, 1u);
        s_last = (d == GRID - 1u) ? 1u : 0u;
    }
    __syncthreads();
    if (s_last) {
        __threadfence();
        float e = g_pent[tid] + g_pent[tid + 256];
        float s = g_pstep[tid] + g_pstep[tid + 256];
#pragma unroll
        for (int o = 16; o; o >>= 1) {
            e += __shfl_xor_sync(0xFFFFFFFFu, e, o);
            s += __shfl_xor_sync(0xFFFFFFFFu, s, o);
        }
        if ((tid & 31) == 0) { wred[tid >> 5] = e; wred[8 + (tid >> 5)] = s; }
        __syncthreads();
        if (tid < 8) {
            e = wred[tid]; s = wred[8 + tid];
#pragma unroll
            for (int o = 4; o; o >>= 1) {
                e += __shfl_xor_sync(0x000000FFu, e, o);
                s += __shfl_xor_sync(0x000000FFu, s, o);
            }
            if (tid == 0) {
                float ent = e / 16384.0f;
                out[131072] = fminf(20.0f, fmaxf(0.0f, ent));
                out[131073] = s / 16384.0f;
                g_done = 0u;   // reset for next launch / graph replay
            }
        }
    }
}

extern "C" void kernel_launch(void* const* d_in, const int* in_sizes, int n_in,
                              void* d_out, int out_size) {
    (void)in_sizes; (void)n_in; (void)out_size;
    const float* x = (const float*)d_in[0];
    const float* W = (const float*)d_in[1];
    const float* b = (const float*)d_in[2];
    float* out = (float*)d_out;

    size_t smem = (16384 + 1024) * sizeof(float);
    cudaFuncSetAttribute(router_kernel, cudaFuncAttributeMaxDynamicSharedMemorySize, (int)smem);
    router_kernel<<<GRID, TPB, smem>>>(x, W, b, out);
}